// round 16
// baseline (speedup 1.0000x reference)
#include <cuda_runtime.h>
#include <cuda_fp16.h>
#include <cstdint>
#include <cstddef>

// ====================== problem constants ======================
#define HW     1024
#define NCONV  2048          // 512 active blocks * 4 tiles (16x16 px)
#define NZERO  1024

// ====================== smem layout (32-bit words) =============
#define S_SCALE_W 0
#define S_BIAS_W  64
#define S_F0_W    128                 // fp16 half: 18*18 px * 16 words = 5184
#define S_F1_W    5312
#define S_WP_W    10496               // fp16 weights: 9216 uint2 = 18432 words
#define S_TOTAL_B 115712              // 28928 words * 4B

// ====================== helpers ================================
__device__ __forceinline__ void mma16(float* c,
                                      uint32_t a0, uint32_t a1, uint32_t a2, uint32_t a3,
                                      uint32_t b0, uint32_t b1) {
    asm volatile(
        "mma.sync.aligned.m16n8k16.row.col.f32.f16.f16.f32 "
        "{%0,%1,%2,%3}, {%4,%5,%6,%7}, {%8,%9}, {%0,%1,%2,%3};"
        : "+f"(c[0]), "+f"(c[1]), "+f"(c[2]), "+f"(c[3])
        : "r"(a0), "r"(a1), "r"(a2), "r"(a3), "r"(b0), "r"(b1));
}

__device__ __forceinline__ uint32_t pack_h2(float lo, float hi) {
    __half2 h = __floats2half2_rn(lo, hi);
    return *(uint32_t*)&h;
}

// named barriers: rendezvous of all 640 threads
__device__ __forceinline__ void barx(int id, int cnt) {
    asm volatile("bar.sync %0, %1;" :: "r"(id), "r"(cnt) : "memory");
}

// ---- producer (128 threads): DIRECT load+convert of ci-half h of the
//      18x18 patch around (gr0-1, gc0-1) into fp16 PACKED-PAIR layout
//      (layout proven R9/R12-R15): word = px*16 + (cig*8+q*2+khalf)^((pcol&2)<<2).
//      Thread-local (LDG -> cvt -> 2x STS.32): no internal barriers needed.
__device__ __forceinline__ void load_half(const float* __restrict__ inp,
                                          int gr0, int gc0, int h,
                                          uint32_t* __restrict__ dst, int ptid) {
    #pragma unroll
    for (int u = 0; u < 21; u++) {
        int f = ptid + u * 128;
        if (u < 20 || ptid < 32) {
            int px = f >> 3, c8 = f & 7;
            int prow = px / 18;
            int pcol = px - prow * 18;
            int ir = gr0 - 1 + prow, ic = gc0 - 1 + pcol;
            int ok = ((unsigned)ir < (unsigned)HW) & ((unsigned)ic < (unsigned)HW);
            const float4* src = (const float4*)(inp
                + ((size_t)(ir & 1023) * HW + (ic & 1023)) * 64 + h * 32 + c8 * 4);
            float4 v = *src;                    // clamped address, always valid
            if (!ok) v = make_float4(0.f, 0.f, 0.f, 0.f);
            int swz = (pcol & 2) << 2;
            int cig = c8 >> 2;
            int cc0 = (4 * c8) & 15;
            int w1 = cig * 8 + ((cc0 & 7) >> 1) * 2 + (cc0 >> 3);
            dst[px * 16 + ( w1      ^ swz)] = pack_h2(v.x, v.y);
            dst[px * 16 + ((w1 + 2) ^ swz)] = pack_h2(v.z, v.w);
        }
    }
}

// ---- consumer: one fully-constant k16 step (KH,KW,CIG literals).
//      Warp tile m32 x n32. All addresses fold to base + immediate.
#define STEPC(KH, KW, CIG, TB)                                              \
{                                                                           \
    const int swz_ = ((grp + (KW)) & 2) << 2;                               \
    const int e_   = (((CIG) << 3) + tq2) ^ swz_;                           \
    const int t_   = ((KH) * 3 + (KW)) * 4 + (TB) + (CIG);                  \
    uint2 B0 = bwl[t_ * 256];                                               \
    uint2 B1 = bwl[t_ * 256 + 32];                                          \
    uint2 B2 = bwl[t_ * 256 + 64];                                          \
    uint2 B3 = bwl[t_ * 256 + 96];                                          \
    _Pragma("unroll")                                                       \
    for (int mf = 0; mf < 2; mf++) {                                        \
        const int w_ = ((rb2 + mf + (KH)) * 18 + grp + (KW)) * 16 + e_;     \
        const uint2 X = pw2[w_ >> 1];                                       \
        const uint2 Y = pw2[(w_ + 128) >> 1];                               \
        mma16(acc[mf][0], X.x, Y.x, X.y, Y.y, B0.x, B0.y);                  \
        mma16(acc[mf][1], X.x, Y.x, X.y, Y.y, B1.x, B1.y);                  \
        mma16(acc[mf][2], X.x, Y.x, X.y, Y.y, B2.x, B2.y);                  \
        mma16(acc[mf][3], X.x, Y.x, X.y, Y.y, B3.x, B3.y);                  \
    }                                                                       \
}

// 18 straight-line k16 steps of one ci-half (TB = H*2).
#define COMPUTE_HALF(FW, TB)                                                \
{                                                                           \
    const uint2* pw2 = (const uint2*)(sm + (FW));                           \
    STEPC(0,0,0,TB) STEPC(0,0,1,TB) STEPC(0,1,0,TB)                         \
    STEPC(0,1,1,TB) STEPC(0,2,0,TB) STEPC(0,2,1,TB)                         \
    STEPC(1,0,0,TB) STEPC(1,0,1,TB) STEPC(1,1,0,TB)                         \
    STEPC(1,1,1,TB) STEPC(1,2,0,TB) STEPC(1,2,1,TB)                         \
    STEPC(2,0,0,TB) STEPC(2,0,1,TB) STEPC(2,1,0,TB)                         \
    STEPC(2,1,1,TB) STEPC(2,2,0,TB) STEPC(2,2,1,TB)                         \
}

// ====================== single fused persistent kernel =========
// 148 CTAs x 640 threads: warps 0-15 = consumers (m32 x n32: 8 m-slots x
// 2 n-halves), warps 16-19 = producers (direct LDG->fp16 convert + zero-fill).
// Item = 16x16 px tile (M=256, N=64, K=576), fp16 mma, f32 accumulate.
__global__ void __launch_bounds__(640, 1)
convk(const float* __restrict__ inp,  const float* __restrict__ w,
      const float* __restrict__ cb,   const float* __restrict__ gm,
      const float* __restrict__ bt,   const float* __restrict__ mn,
      const float* __restrict__ vr,   const int* __restrict__ abi,
      float* __restrict__ out) {
    extern __shared__ float sm[];
    const int tid  = threadIdx.x;
    const int wid  = tid >> 5;
    const int lane = tid & 31;
    const int grp  = lane >> 2;
    const int q    = lane & 3;
    const int tq2  = q * 2;

    // ---- all threads: stage fp16 weights [t][nf][grp][q] + scale/bias ----
    {
        uint2* wsm = (uint2*)(sm + S_WP_W);
        #pragma unroll 2
        for (int idx = tid; idx < 9216; idx += 640) {
            int qq = idx & 3;
            int gg = (idx >> 2) & 7;
            int nf = (idx >> 5) & 7;
            int t  = idx >> 8;
            int n  = nf * 8 + gg;
            int k0 = 16 * t + 2 * qq;
            uint2 o;
            o.x = pack_h2(w[k0 * 64 + n],       w[(k0 + 1) * 64 + n]);
            o.y = pack_h2(w[(k0 + 8) * 64 + n], w[(k0 + 9) * 64 + n]);
            wsm[idx] = o;
        }
        if (tid < 64) {
            float s = gm[tid] * rsqrtf(vr[tid] + 1e-3f);
            sm[S_SCALE_W + tid] = s;
            sm[S_BIAS_W + tid]  = cb[tid] * s + bt[tid] - mn[tid] * s;
        }
        __syncthreads();
    }

    if (wid < 16) {
        // ============ CONSUMERS (16 warps: m-slot x n-half) ============
        const int rb2 = (wid >> 1) * 2;          // px-row base (2 of 16)
        const int nb  = (wid & 1) * 128;         // n-half offset (uint2 units)
        const uint2* bwl = (const uint2*)(sm + S_WP_W) + nb + lane;

        for (int it = blockIdx.x; it < NCONV; it += gridDim.x) {
            const int b = it >> 2, sub = it & 3;
            const int gr0 = abi[3 * b + 1] * 32 + (sub >> 1) * 16;
            const int gc0 = abi[3 * b + 2] * 32 + (sub & 1) * 16;

            float acc[2][4][4];
            #pragma unroll
            for (int a = 0; a < 2; a++)
                #pragma unroll
                for (int c = 0; c < 4; c++)
                    #pragma unroll
                    for (int d = 0; d < 4; d++) acc[a][c][d] = 0.f;

            barx(1, 640);                        // F0 ready
            COMPUTE_HALF(S_F0_W, 0)
            barx(2, 640);                        // F1 ready
            COMPUTE_HALF(S_F1_W, 2)

            // ---- epilogue: fused BN scale/bias + ReLU (this n-half) ----
            #pragma unroll
            for (int mf = 0; mf < 2; mf++) {
                const int gpr = gr0 + rb2 + mf;
                #pragma unroll
                for (int nf = 0; nf < 4; nf++) {
                    const int n0 = (wid & 1) * 32 + nf * 8 + 2 * q;
                    const float s0 = sm[S_SCALE_W + n0], s1 = sm[S_SCALE_W + n0 + 1];
                    const float d0 = sm[S_BIAS_W + n0],  d1 = sm[S_BIAS_W + n0 + 1];
                    float* p0 = out + ((size_t)gpr * HW + gc0 + grp) * 64 + n0;
                    float2 v0, v1;
                    v0.x = fmaxf(fmaf(acc[mf][nf][0], s0, d0), 0.f);
                    v0.y = fmaxf(fmaf(acc[mf][nf][1], s1, d1), 0.f);
                    v1.x = fmaxf(fmaf(acc[mf][nf][2], s0, d0), 0.f);
                    v1.y = fmaxf(fmaf(acc[mf][nf][3], s1, d1), 0.f);
                    __stcs((float2*)p0, v0);
                    __stcs((float2*)(p0 + 8 * 64), v1);    // px col grp+8
                }
            }
        }
    } else {
        // ============ PRODUCERS (4 warps, 128 thr) ============
        const int ptid = tid - 512;              // 0..127
        int zit = blockIdx.x, zchunk = 0, zok = -1;

        for (int it = blockIdx.x; it < NCONV; it += gridDim.x) {
            const int b = it >> 2, sub = it & 3;
            const int gr0 = abi[3 * b + 1] * 32 + (sub >> 1) * 16;
            const int gc0 = abi[3 * b + 2] * 32 + (sub & 1) * 16;

            // F0 write is safe: consumers finished F0 reads at barx(2) of
            // the previous item (or haven't started, first iteration).
            load_half(inp, gr0, gc0, 0, (uint32_t*)(sm + S_F0_W), ptid);
            barx(1, 640);                        // publish F0
            load_half(inp, gr0, gc0, 1, (uint32_t*)(sm + S_F1_W), ptid);
            barx(2, 640);                        // publish F1

            // ---- slack: up to 2 zero-fill chunks (4 px rows each) ----
            #pragma unroll 1
            for (int zc = 0; zc < 2 && zit < NZERO; ) {
                if (zchunk == 0 && zok < 0) {
                    int lo = 0, hi = 511, found = 0;
                    while (lo <= hi) {
                        int mid = (lo + hi) >> 1;
                        int f = abi[3 * mid + 1] * 32 + abi[3 * mid + 2];
                        if (f == zit) { found = 1; break; }
                        if (f < zit) lo = mid + 1; else hi = mid - 1;
                    }
                    zok = found ? 0 : 1;
                    if (!zok) { zit += gridDim.x; zok = -1; continue; }
                }
                const int bi = zit >> 5, bj = zit & 31;
                const float4 z = make_float4(0.f, 0.f, 0.f, 0.f);
                #pragma unroll 8
                for (int j = 0; j < 16; j++) {
                    int idx = ptid + j * 128;    // 2048 f4 = 4 px rows
                    int r   = zchunk * 4 + (idx >> 9);
                    int c4  = idx & 511;
                    __stcs((float4*)(out + ((size_t)(bi * 32 + r) * HW + bj * 32) * 64) + c4, z);
                }
                if (++zchunk == 8) { zchunk = 0; zok = -1; zit += gridDim.x; }
                zc++;
            }
        }
        // ---- tail: finish remaining zero-fill ----
        while (zit < NZERO) {
            if (zchunk == 0 && zok < 0) {
                int lo = 0, hi = 511, found = 0;
                while (lo <= hi) {
                    int mid = (lo + hi) >> 1;
                    int f = abi[3 * mid + 1] * 32 + abi[3 * mid + 2];
                    if (f == zit) { found = 1; break; }
                    if (f < zit) lo = mid + 1; else hi = mid - 1;
                }
                zok = found ? 0 : 1;
                if (!zok) { zit += gridDim.x; zok = -1; continue; }
            }
            const int bi = zit >> 5, bj = zit & 31;
            const float4 z = make_float4(0.f, 0.f, 0.f, 0.f);
            #pragma unroll 8
            for (int j = 0; j < 16; j++) {
                int idx = ptid + j * 128;
                int r   = zchunk * 4 + (idx >> 9);
                int c4  = idx & 511;
                __stcs((float4*)(out + ((size_t)(bi * 32 + r) * HW + bj * 32) * 64) + c4, z);
            }
            if (++zchunk == 8) { zchunk = 0; zok = -1; zit += gridDim.x; }
        }
    }
}

// ====================== launch =================================
extern "C" void kernel_launch(void* const* d_in, const int* in_sizes, int n_in,
                              void* d_out, int out_size) {
    const float* inp   = (const float*)d_in[0];
    const float* w     = (const float*)d_in[1];
    const float* cb    = (const float*)d_in[2];
    const float* gamma = (const float*)d_in[3];
    const float* beta  = (const float*)d_in[4];
    const float* mean  = (const float*)d_in[5];
    const float* var   = (const float*)d_in[6];
    const int*   abi   = (const int*)d_in[7];
    float* out = (float*)d_out;

    cudaFuncSetAttribute(convk, cudaFuncAttributeMaxDynamicSharedMemorySize, S_TOTAL_B);
    convk<<<148, 640, S_TOTAL_B>>>(inp, w, cb, gamma, beta, mean, var, abi, out);
}

// round 17
// speedup vs baseline: 1.4599x; 1.4599x over previous
#include <cuda_runtime.h>
#include <cuda_fp16.h>
#include <cstdint>
#include <cstddef>

// ====================== problem constants ======================
#define HW     1024
#define NCONV  2048          // 512 active blocks * 4 tiles (16x16 px)
#define NZERO  1024

// ====================== smem layout (32-bit words) =============
#define S_SCALE_W 0
#define S_BIAS_W  64
#define S_STG_W   128                 // f32 stage: 18*18 px * 32 ch = 10368 words
#define S_F0_W    10496               // fp16 half: 18*18 px * 16 words = 5184
#define S_F1_W    15680
#define S_WP_W    20864               // fp16 weights: 9216 uint2 = 18432 words
#define S_TOTAL_B 157184              // 39296 words * 4B

// ====================== helpers ================================
__device__ __forceinline__ void mma16(float* c,
                                      uint32_t a0, uint32_t a1, uint32_t a2, uint32_t a3,
                                      uint32_t b0, uint32_t b1) {
    asm volatile(
        "mma.sync.aligned.m16n8k16.row.col.f32.f16.f16.f32 "
        "{%0,%1,%2,%3}, {%4,%5,%6,%7}, {%8,%9}, {%0,%1,%2,%3};"
        : "+f"(c[0]), "+f"(c[1]), "+f"(c[2]), "+f"(c[3])
        : "r"(a0), "r"(a1), "r"(a2), "r"(a3), "r"(b0), "r"(b1));
}

__device__ __forceinline__ uint32_t pack_h2(float lo, float hi) {
    __half2 h = __floats2half2_rn(lo, hi);
    return *(uint32_t*)&h;
}

__device__ __forceinline__ void cp_async16(uint32_t dst_smem, const void* src, int src_sz) {
    asm volatile("cp.async.cg.shared.global [%0], [%1], 16, %2;"
                 :: "r"(dst_smem), "l"(src), "r"(src_sz) : "memory");
}
__device__ __forceinline__ void cp_commit() {
    asm volatile("cp.async.commit_group;" ::: "memory");
}
__device__ __forceinline__ void cp_wait0() {
    asm volatile("cp.async.wait_group 0;" ::: "memory");
}
// named barriers: rendezvous (640) or producer-only (128)
__device__ __forceinline__ void barx(int id, int cnt) {
    asm volatile("bar.sync %0, %1;" :: "r"(id), "r"(cnt) : "memory");
}

// ---- producer (128 threads): cp.async of ci-half h of the 18x18 patch
//      around (gr0-1, gc0-1) into the f32 stage. 2592 float4.  (proven R14/R15)
__device__ __forceinline__ void issue_half(const float* __restrict__ inp,
                                           int gr0, int gc0, int h,
                                           uint32_t stgb, int ptid) {
    #pragma unroll
    for (int u = 0; u < 21; u++) {
        int f = ptid + u * 128;
        if (u < 20 || ptid < 32) {
            int px = f >> 3, c8 = f & 7;
            int prow = px / 18;
            int pcol = px - prow * 18;
            int ir = gr0 - 1 + prow, ic = gc0 - 1 + pcol;
            int ok = ((unsigned)ir < (unsigned)HW) & ((unsigned)ic < (unsigned)HW);
            const float* src = inp + ((size_t)(ir & 1023) * HW + (ic & 1023)) * 64
                               + h * 32 + c8 * 4;
            cp_async16(stgb + f * 16, src, ok ? 16 : 0);
        }
    }
    cp_commit();
}

// ---- producer: convert staged f32 half -> fp16 PACKED-PAIR layout
//      (proven R9/R12-R15): word = px*16 + (cig*8+q*2+khalf) ^ ((pcol&2)<<2).
__device__ __forceinline__ void convert_half(const float* __restrict__ stg,
                                             uint32_t* __restrict__ dst, int ptid) {
    #pragma unroll
    for (int u = 0; u < 21; u++) {
        int f = ptid + u * 128;
        if (u < 20 || ptid < 32) {
            float4 v = ((const float4*)stg)[f];
            int px = f >> 3, c8 = f & 7;
            int pcol = px % 18;
            int swz = (pcol & 2) << 2;
            int cig = c8 >> 2;
            int cc0 = (4 * c8) & 15;
            int w1 = cig * 8 + ((cc0 & 7) >> 1) * 2 + (cc0 >> 3);
            dst[px * 16 + ( w1      ^ swz)] = pack_h2(v.x, v.y);
            dst[px * 16 + ((w1 + 2) ^ swz)] = pack_h2(v.z, v.w);
        }
    }
}

// ---- consumer: one fully-constant k16 step (KH,KW,CIG literals; proven R16).
//      Warp tile m32 x n32. All addresses fold to base + immediate.
#define STEPC(KH, KW, CIG, TB)                                              \
{                                                                           \
    const int swz_ = ((grp + (KW)) & 2) << 2;                               \
    const int e_   = (((CIG) << 3) + tq2) ^ swz_;                           \
    const int t_   = ((KH) * 3 + (KW)) * 4 + (TB) + (CIG);                  \
    uint2 B0 = bwl[t_ * 256];                                               \
    uint2 B1 = bwl[t_ * 256 + 32];                                          \
    uint2 B2 = bwl[t_ * 256 + 64];                                          \
    uint2 B3 = bwl[t_ * 256 + 96];                                          \
    _Pragma("unroll")                                                       \
    for (int mf = 0; mf < 2; mf++) {                                        \
        const int w_ = ((rb2 + mf + (KH)) * 18 + grp + (KW)) * 16 + e_;     \
        const uint2 X = pw2[w_ >> 1];                                       \
        const uint2 Y = pw2[(w_ + 128) >> 1];                               \
        mma16(acc[mf][0], X.x, Y.x, X.y, Y.y, B0.x, B0.y);                  \
        mma16(acc[mf][1], X.x, Y.x, X.y, Y.y, B1.x, B1.y);                  \
        mma16(acc[mf][2], X.x, Y.x, X.y, Y.y, B2.x, B2.y);                  \
        mma16(acc[mf][3], X.x, Y.x, X.y, Y.y, B3.x, B3.y);                  \
    }                                                                       \
}

// 18 straight-line k16 steps of one ci-half (TB = H*2).
#define COMPUTE_HALF(FW, TB)                                                \
{                                                                           \
    const uint2* pw2 = (const uint2*)(sm + (FW));                           \
    STEPC(0,0,0,TB) STEPC(0,0,1,TB) STEPC(0,1,0,TB)                         \
    STEPC(0,1,1,TB) STEPC(0,2,0,TB) STEPC(0,2,1,TB)                         \
    STEPC(1,0,0,TB) STEPC(1,0,1,TB) STEPC(1,1,0,TB)                         \
    STEPC(1,1,1,TB) STEPC(1,2,0,TB) STEPC(1,2,1,TB)                         \
    STEPC(2,0,0,TB) STEPC(2,0,1,TB) STEPC(2,1,0,TB)                         \
    STEPC(2,1,1,TB) STEPC(2,2,0,TB) STEPC(2,2,1,TB)                         \
}

// ====================== single fused persistent kernel =========
// 148 CTAs x 640 threads: warps 0-15 = consumers (m32 x n32: 8 m-slots x
// 2 n-halves, straight-line K loop), warps 16-19 = producers (async
// cp.async + convert + zero-fill). Item = 16x16 px tile (M=256,N=64,K=576).
__global__ void __launch_bounds__(640, 1)
convk(const float* __restrict__ inp,  const float* __restrict__ w,
      const float* __restrict__ cb,   const float* __restrict__ gm,
      const float* __restrict__ bt,   const float* __restrict__ mn,
      const float* __restrict__ vr,   const int* __restrict__ abi,
      float* __restrict__ out) {
    extern __shared__ float sm[];
    const int tid  = threadIdx.x;
    const int wid  = tid >> 5;
    const int lane = tid & 31;
    const int grp  = lane >> 2;
    const int q    = lane & 3;
    const int tq2  = q * 2;

    uint32_t smem_u32;
    asm("{ .reg .u64 t; cvta.to.shared.u64 t, %1; cvt.u32.u64 %0, t; }"
        : "=r"(smem_u32) : "l"((const void*)sm));
    const uint32_t stg_u32 = smem_u32 + S_STG_W * 4;

    // ---- all threads: stage fp16 weights [t][nf][grp][q] + scale/bias ----
    {
        uint2* wsm = (uint2*)(sm + S_WP_W);
        #pragma unroll 2
        for (int idx = tid; idx < 9216; idx += 640) {
            int qq = idx & 3;
            int gg = (idx >> 2) & 7;
            int nf = (idx >> 5) & 7;
            int t  = idx >> 8;
            int n  = nf * 8 + gg;
            int k0 = 16 * t + 2 * qq;
            uint2 o;
            o.x = pack_h2(w[k0 * 64 + n],       w[(k0 + 1) * 64 + n]);
            o.y = pack_h2(w[(k0 + 8) * 64 + n], w[(k0 + 9) * 64 + n]);
            wsm[idx] = o;
        }
        if (tid < 64) {
            float s = gm[tid] * rsqrtf(vr[tid] + 1e-3f);
            sm[S_SCALE_W + tid] = s;
            sm[S_BIAS_W + tid]  = cb[tid] * s + bt[tid] - mn[tid] * s;
        }
        __syncthreads();
    }

    if (wid < 16) {
        // ============ CONSUMERS (16 warps: m-slot x n-half) ============
        const int rb2 = (wid >> 1) * 2;          // px-row base (2 of 16)
        const int nb  = (wid & 1) * 128;         // n-half offset (uint2 units)
        const uint2* bwl = (const uint2*)(sm + S_WP_W) + nb + lane;

        for (int it = blockIdx.x; it < NCONV; it += gridDim.x) {
            const int b = it >> 2, sub = it & 3;
            const int gr0 = abi[3 * b + 1] * 32 + (sub >> 1) * 16;
            const int gc0 = abi[3 * b + 2] * 32 + (sub & 1) * 16;

            float acc[2][4][4];
            #pragma unroll
            for (int a = 0; a < 2; a++)
                #pragma unroll
                for (int c = 0; c < 4; c++)
                    #pragma unroll
                    for (int d = 0; d < 4; d++) acc[a][c][d] = 0.f;

            barx(1, 640);                        // F0 ready
            COMPUTE_HALF(S_F0_W, 0)
            barx(2, 640);                        // F1 ready
            COMPUTE_HALF(S_F1_W, 2)

            // ---- epilogue: fused BN scale/bias + ReLU (this n-half) ----
            #pragma unroll
            for (int mf = 0; mf < 2; mf++) {
                const int gpr = gr0 + rb2 + mf;
                #pragma unroll
                for (int nf = 0; nf < 4; nf++) {
                    const int n0 = (wid & 1) * 32 + nf * 8 + 2 * q;
                    const float s0 = sm[S_SCALE_W + n0], s1 = sm[S_SCALE_W + n0 + 1];
                    const float d0 = sm[S_BIAS_W + n0],  d1 = sm[S_BIAS_W + n0 + 1];
                    float* p0 = out + ((size_t)gpr * HW + gc0 + grp) * 64 + n0;
                    float2 v0, v1;
                    v0.x = fmaxf(fmaf(acc[mf][nf][0], s0, d0), 0.f);
                    v0.y = fmaxf(fmaf(acc[mf][nf][1], s1, d1), 0.f);
                    v1.x = fmaxf(fmaf(acc[mf][nf][2], s0, d0), 0.f);
                    v1.y = fmaxf(fmaf(acc[mf][nf][3], s1, d1), 0.f);
                    __stcs((float2*)p0, v0);
                    __stcs((float2*)(p0 + 8 * 64), v1);    // px col grp+8
                }
            }
        }
    } else {
        // ============ PRODUCERS (4 warps, 128 thr) — proven R15 ============
        const int ptid = tid - 512;              // 0..127
        int zit = blockIdx.x, zchunk = 0, zok = -1;

        {   // prologue: issue first item's half0
            const int it0 = blockIdx.x;          // < NCONV
            const int b = it0 >> 2, sub = it0 & 3;
            issue_half(inp, abi[3 * b + 1] * 32 + (sub >> 1) * 16,
                       abi[3 * b + 2] * 32 + (sub & 1) * 16, 0, stg_u32, ptid);
        }

        for (int it = blockIdx.x; it < NCONV; it += gridDim.x) {
            const int b = it >> 2, sub = it & 3;
            const int gr0 = abi[3 * b + 1] * 32 + (sub >> 1) * 16;
            const int gc0 = abi[3 * b + 2] * 32 + (sub & 1) * 16;

            cp_wait0();  barx(3, 128);           // h0 staged, all producers
            convert_half(sm + S_STG_W, (uint32_t*)(sm + S_F0_W), ptid);
            barx(3, 128);                        // stage reads done
            issue_half(inp, gr0, gc0, 1, stg_u32, ptid);
            barx(1, 640);                        // publish F0

            cp_wait0();  barx(3, 128);
            convert_half(sm + S_STG_W, (uint32_t*)(sm + S_F1_W), ptid);
            barx(3, 128);
            const int itn = it + gridDim.x;
            if (itn < NCONV) {
                const int bn = itn >> 2, sn = itn & 3;
                issue_half(inp, abi[3 * bn + 1] * 32 + (sn >> 1) * 16,
                           abi[3 * bn + 2] * 32 + (sn & 1) * 16, 0, stg_u32, ptid);
            }
            barx(2, 640);                        // publish F1

            // ---- slack: up to 2 zero-fill chunks (4 px rows each) ----
            #pragma unroll 1
            for (int zc = 0; zc < 2 && zit < NZERO; ) {
                if (zchunk == 0 && zok < 0) {
                    int lo = 0, hi = 511, found = 0;
                    while (lo <= hi) {
                        int mid = (lo + hi) >> 1;
                        int f = abi[3 * mid + 1] * 32 + abi[3 * mid + 2];
                        if (f == zit) { found = 1; break; }
                        if (f < zit) lo = mid + 1; else hi = mid - 1;
                    }
                    zok = found ? 0 : 1;
                    if (!zok) { zit += gridDim.x; zok = -1; continue; }
                }
                const int bi = zit >> 5, bj = zit & 31;
                const float4 z = make_float4(0.f, 0.f, 0.f, 0.f);
                #pragma unroll 8
                for (int j = 0; j < 16; j++) {
                    int idx = ptid + j * 128;    // 2048 f4 = 4 px rows
                    int r   = zchunk * 4 + (idx >> 9);
                    int c4  = idx & 511;
                    __stcs((float4*)(out + ((size_t)(bi * 32 + r) * HW + bj * 32) * 64) + c4, z);
                }
                if (++zchunk == 8) { zchunk = 0; zok = -1; zit += gridDim.x; }
                zc++;
            }
        }
        // ---- tail: finish remaining zero-fill ----
        while (zit < NZERO) {
            if (zchunk == 0 && zok < 0) {
                int lo = 0, hi = 511, found = 0;
                while (lo <= hi) {
                    int mid = (lo + hi) >> 1;
                    int f = abi[3 * mid + 1] * 32 + abi[3 * mid + 2];
                    if (f == zit) { found = 1; break; }
                    if (f < zit) lo = mid + 1; else hi = mid - 1;
                }
                zok = found ? 0 : 1;
                if (!zok) { zit += gridDim.x; zok = -1; continue; }
            }
            const int bi = zit >> 5, bj = zit & 31;
            const float4 z = make_float4(0.f, 0.f, 0.f, 0.f);
            #pragma unroll 8
            for (int j = 0; j < 16; j++) {
                int idx = ptid + j * 128;
                int r   = zchunk * 4 + (idx >> 9);
                int c4  = idx & 511;
                __stcs((float4*)(out + ((size_t)(bi * 32 + r) * HW + bj * 32) * 64) + c4, z);
            }
            if (++zchunk == 8) { zchunk = 0; zok = -1; zit += gridDim.x; }
        }
        cp_wait0();                              // drain in-flight cp.async
    }
}

// ====================== launch =================================
extern "C" void kernel_launch(void* const* d_in, const int* in_sizes, int n_in,
                              void* d_out, int out_size) {
    const float* inp   = (const float*)d_in[0];
    const float* w     = (const float*)d_in[1];
    const float* cb    = (const float*)d_in[2];
    const float* gamma = (const float*)d_in[3];
    const float* beta  = (const float*)d_in[4];
    const float* mean  = (const float*)d_in[5];
    const float* var   = (const float*)d_in[6];
    const int*   abi   = (const int*)d_in[7];
    float* out = (float*)d_out;

    cudaFuncSetAttribute(convk, cudaFuncAttributeMaxDynamicSharedMemorySize, S_TOTAL_B);
    convk<<<148, 640, S_TOTAL_B>>>(inp, w, cb, gamma, beta, mean, var, abi, out);
}